// round 1
// baseline (speedup 1.0000x reference)
#include <cuda_runtime.h>
#include <math.h>

#define N 512
#define D 256

// Scratch (allocation-free rule: __device__ globals)
__device__ float g_dist[N * N];   // 1 MB distance matrix
__device__ float g_sq[N];         // squared norms
__device__ float g_psum[N];       // per-anchor partial sums
__device__ float g_pcnt[N];       // per-anchor partial counts

// ---------------------------------------------------------------------------
// Kernel 0: squared norms  sq[i] = sum_k x[i,k]^2
// ---------------------------------------------------------------------------
__global__ void sq_kernel(const float* __restrict__ x) {
    int i = blockIdx.x * blockDim.x + threadIdx.x;
    if (i < N) {
        const float4* row = reinterpret_cast<const float4*>(x + i * D);
        float s = 0.f;
#pragma unroll
        for (int k = 0; k < D / 4; k++) {
            float4 v = row[k];
            s += v.x * v.x + v.y * v.y + v.z * v.z + v.w * v.w;
        }
        g_sq[i] = s;
    }
}

// ---------------------------------------------------------------------------
// Kernel 1: dist[i,j] = sqrt(max(sq_i + sq_j - 2*dot(x_i,x_j), 1e-16))
// Mini-SGEMM: BM=BN=64, BK=16, 16x16 threads, 4x4 register tile.
// ---------------------------------------------------------------------------
__global__ void dist_kernel(const float* __restrict__ x) {
    __shared__ float As[16][64];  // [k][m]
    __shared__ float Bs[16][64];  // [k][n]

    const int tx = threadIdx.x;        // 0..15
    const int ty = threadIdx.y;        // 0..15
    const int tid = ty * 16 + tx;
    const int i0 = blockIdx.y * 64;
    const int j0 = blockIdx.x * 64;

    const int lm = tid >> 2;           // 0..63 row within tile
    const int lk = (tid & 3) << 2;     // 0,4,8,12 k offset

    float acc[4][4];
#pragma unroll
    for (int r = 0; r < 4; r++)
#pragma unroll
        for (int c = 0; c < 4; c++) acc[r][c] = 0.f;

    for (int kk = 0; kk < D; kk += 16) {
        float4 av = *reinterpret_cast<const float4*>(x + (i0 + lm) * D + kk + lk);
        float4 bv = *reinterpret_cast<const float4*>(x + (j0 + lm) * D + kk + lk);
        As[lk + 0][lm] = av.x; As[lk + 1][lm] = av.y;
        As[lk + 2][lm] = av.z; As[lk + 3][lm] = av.w;
        Bs[lk + 0][lm] = bv.x; Bs[lk + 1][lm] = bv.y;
        Bs[lk + 2][lm] = bv.z; Bs[lk + 3][lm] = bv.w;
        __syncthreads();

#pragma unroll
        for (int k = 0; k < 16; k++) {
            float4 a = *reinterpret_cast<const float4*>(&As[k][ty * 4]);
            float4 b = *reinterpret_cast<const float4*>(&Bs[k][tx * 4]);
            acc[0][0] += a.x * b.x; acc[0][1] += a.x * b.y; acc[0][2] += a.x * b.z; acc[0][3] += a.x * b.w;
            acc[1][0] += a.y * b.x; acc[1][1] += a.y * b.y; acc[1][2] += a.y * b.z; acc[1][3] += a.y * b.w;
            acc[2][0] += a.z * b.x; acc[2][1] += a.z * b.y; acc[2][2] += a.z * b.z; acc[2][3] += a.z * b.w;
            acc[3][0] += a.w * b.x; acc[3][1] += a.w * b.y; acc[3][2] += a.w * b.z; acc[3][3] += a.w * b.w;
        }
        __syncthreads();
    }

    float si[4], sj[4];
#pragma unroll
    for (int r = 0; r < 4; r++) si[r] = g_sq[i0 + ty * 4 + r];
#pragma unroll
    for (int c = 0; c < 4; c++) sj[c] = g_sq[j0 + tx * 4 + c];

#pragma unroll
    for (int r = 0; r < 4; r++) {
        int i = i0 + ty * 4 + r;
#pragma unroll
        for (int c = 0; c < 4; c++) {
            int j = j0 + tx * 4 + c;
            float v = si[r] + sj[c] - 2.f * acc[r][c];
            g_dist[i * N + j] = sqrtf(fmaxf(v, 1e-16f));
        }
    }
}

// ---------------------------------------------------------------------------
// Kernel 2: per-anchor triplet reduction. One block per anchor i.
//   For valid (j: l[j]==l[i], j!=i) x (k: l[k]!=l[i]):
//     v = d[i,j] - d[i,k] + 1;  sum += max(v,0);  cnt += (v > 1e-16)
// Deterministic shuffle + smem reduction.
// ---------------------------------------------------------------------------
__global__ void triplet_kernel(const int* __restrict__ labels) {
    __shared__ float drow[N];
    __shared__ int   lab[N];
    __shared__ float sred[8];
    __shared__ int   cred[8];

    const int i = blockIdx.x;
    const int t = threadIdx.x;  // 0..255

    drow[t]       = g_dist[i * N + t];
    drow[t + 256] = g_dist[i * N + t + 256];
    lab[t]        = labels[t];
    lab[t + 256]  = labels[t + 256];
    __syncthreads();

    const int li = lab[i];
    const float d0 = drow[t];
    const float d1 = drow[t + 256];
    const bool n0 = (lab[t] != li);
    const bool n1 = (lab[t + 256] != li);

    float sum = 0.f;
    int cnt = 0;

    for (int j = 0; j < N; j++) {
        if (lab[j] == li && j != i) {        // uniform branch across block
            float a = drow[j] + 1.0f;        // d_ij + margin
            if (n0) {
                float v = a - d0;
                if (v > 0.f) sum += v;
                if (v > 1e-16f) cnt++;
            }
            if (n1) {
                float v = a - d1;
                if (v > 0.f) sum += v;
                if (v > 1e-16f) cnt++;
            }
        }
    }

    // deterministic reduction
    const int lane = t & 31;
    const int warp = t >> 5;
#pragma unroll
    for (int o = 16; o > 0; o >>= 1) {
        sum += __shfl_down_sync(0xFFFFFFFFu, sum, o);
        cnt += __shfl_down_sync(0xFFFFFFFFu, cnt, o);
    }
    if (lane == 0) { sred[warp] = sum; cred[warp] = cnt; }
    __syncthreads();
    if (t == 0) {
        float s = 0.f; int c = 0;
#pragma unroll
        for (int w = 0; w < 8; w++) { s += sred[w]; c += cred[w]; }
        g_psum[i] = s;
        g_pcnt[i] = (float)c;
    }
}

// ---------------------------------------------------------------------------
// Kernel 3: final deterministic reduction of 512 partials -> scalar
// ---------------------------------------------------------------------------
__global__ void final_kernel(float* __restrict__ out) {
    __shared__ float sred[8];
    __shared__ float cred[8];

    const int t = threadIdx.x;  // 0..255
    float s = g_psum[t] + g_psum[t + 256];
    float c = g_pcnt[t] + g_pcnt[t + 256];

    const int lane = t & 31;
    const int warp = t >> 5;
#pragma unroll
    for (int o = 16; o > 0; o >>= 1) {
        s += __shfl_down_sync(0xFFFFFFFFu, s, o);
        c += __shfl_down_sync(0xFFFFFFFFu, c, o);
    }
    if (lane == 0) { sred[warp] = s; cred[warp] = c; }
    __syncthreads();
    if (t == 0) {
        float S = 0.f, C = 0.f;
#pragma unroll
        for (int w = 0; w < 8; w++) { S += sred[w]; C += cred[w]; }
        out[0] = S / (C + 1e-16f);
    }
}

// ---------------------------------------------------------------------------
extern "C" void kernel_launch(void* const* d_in, const int* in_sizes, int n_in,
                              void* d_out, int out_size) {
    const float* x      = (const float*)d_in[0];   // (512, 256) float32
    const int*   labels = (const int*)d_in[1];     // (512,) int32
    float* out = (float*)d_out;

    sq_kernel<<<2, 256>>>(x);
    {
        dim3 grid(8, 8), block(16, 16);
        dist_kernel<<<grid, block>>>(x);
    }
    triplet_kernel<<<N, 256>>>(labels);
    final_kernel<<<1, 256>>>(out);
}

// round 2
// speedup vs baseline: 2.8604x; 2.8604x over previous
#include <cuda_runtime.h>
#include <math.h>

#define N 512
#define D 256
#define BT 32   // dist tile edge

// Scratch (__device__ globals per allocation-free rule)
__device__ float g_dist[N * N];
__device__ float g_psum[N];
__device__ float g_pcnt[N];
__device__ int   g_done = 0;

// ---------------------------------------------------------------------------
// Kernel 1: fused sq-norms + symmetric distance matrix.
// Triangular grid: 136 blocks cover the 16x16 upper triangle of 32x32 tiles.
// Each block: computes sq for its 64 rows, 32x32 GEMM tile, writes tile+mirror.
// ---------------------------------------------------------------------------
__global__ void dist_kernel(const float* __restrict__ x) {
    __shared__ float As[BT][BT + 1];  // [m][k], pad 33 -> conflict-free reads
    __shared__ float Bs[BT][BT + 1];
    __shared__ float sqi[BT];
    __shared__ float sqj[BT];

    // linear block id -> triangle (bi >= bj)
    int b = blockIdx.x;
    int bi = (int)((sqrtf(8.f * (float)b + 1.f) - 1.f) * 0.5f);
    while ((bi + 1) * (bi + 2) / 2 <= b) bi++;
    while (bi * (bi + 1) / 2 > b) bi--;
    int bj = b - bi * (bi + 1) / 2;
    const int i0 = bi * BT;
    const int j0 = bj * BT;

    const int t = threadIdx.x;      // 0..255
    const int lane = t & 31;
    const int w = t >> 5;           // 0..7

    // --- sq phase: warp w handles 8 of the 64 rows (first 32 = i-rows) ---
#pragma unroll
    for (int rr = 0; rr < 8; rr++) {
        int r = w * 8 + rr;                         // 0..63
        int gr = (r < 32) ? (i0 + r) : (j0 + r - 32);
        const float* row = x + gr * D;
        float s = 0.f;
#pragma unroll
        for (int n = 0; n < 8; n++) { float v = row[lane + 32 * n]; s += v * v; }
#pragma unroll
        for (int o = 16; o > 0; o >>= 1) s += __shfl_down_sync(0xFFFFFFFFu, s, o);
        if (lane == 0) { if (r < 32) sqi[r] = s; else sqj[r - 32] = s; }
    }

    // --- GEMM phase: 16x16 threads, 2x2 register tile each ---
    const int tx = t & 15;
    const int ty = t >> 4;
    const int lr = t >> 3;            // loader row 0..31
    const int lc = (t & 7) * 4;       // loader col (float) 0,4,..28

    float acc00 = 0.f, acc01 = 0.f, acc10 = 0.f, acc11 = 0.f;

    for (int kk = 0; kk < D; kk += BT) {
        float4 av = *reinterpret_cast<const float4*>(x + (i0 + lr) * D + kk + lc);
        float4 bv = *reinterpret_cast<const float4*>(x + (j0 + lr) * D + kk + lc);
        As[lr][lc + 0] = av.x; As[lr][lc + 1] = av.y;
        As[lr][lc + 2] = av.z; As[lr][lc + 3] = av.w;
        Bs[lr][lc + 0] = bv.x; Bs[lr][lc + 1] = bv.y;
        Bs[lr][lc + 2] = bv.z; Bs[lr][lc + 3] = bv.w;
        __syncthreads();

#pragma unroll
        for (int k = 0; k < BT; k++) {
            float a0 = As[2 * ty + 0][k];
            float a1 = As[2 * ty + 1][k];
            float b0 = Bs[2 * tx + 0][k];
            float b1 = Bs[2 * tx + 1][k];
            acc00 += a0 * b0; acc01 += a0 * b1;
            acc10 += a1 * b0; acc11 += a1 * b1;
        }
        __syncthreads();
    }

    // --- epilogue: dist + mirror write (sq phase done: many syncs passed) ---
    const int i = i0 + 2 * ty;
    const int j = j0 + 2 * tx;
    float si0 = sqi[2 * ty], si1 = sqi[2 * ty + 1];
    float sj0 = sqj[2 * tx], sj1 = sqj[2 * tx + 1];

    float d00 = sqrtf(fmaxf(si0 + sj0 - 2.f * acc00, 1e-16f));
    float d01 = sqrtf(fmaxf(si0 + sj1 - 2.f * acc01, 1e-16f));
    float d10 = sqrtf(fmaxf(si1 + sj0 - 2.f * acc10, 1e-16f));
    float d11 = sqrtf(fmaxf(si1 + sj1 - 2.f * acc11, 1e-16f));

    g_dist[(i    ) * N + j    ] = d00;
    g_dist[(i    ) * N + j + 1] = d01;
    g_dist[(i + 1) * N + j    ] = d10;
    g_dist[(i + 1) * N + j + 1] = d11;
    // mirror (diagonal blocks: duplicate same-value writes, benign)
    g_dist[(j    ) * N + i    ] = d00;
    g_dist[(j + 1) * N + i    ] = d01;
    g_dist[(j    ) * N + i + 1] = d10;
    g_dist[(j + 1) * N + i + 1] = d11;
}

// ---------------------------------------------------------------------------
// Kernel 2: per-anchor triplet reduction with positive-list compaction,
// fused final reduction via last-block-done counter (deterministic).
// ---------------------------------------------------------------------------
__global__ void triplet_kernel(const int* __restrict__ labels,
                               float* __restrict__ out) {
    __shared__ float drow[N];
    __shared__ int   lab[N];
    __shared__ int   segcnt[16];
    __shared__ int   posj[N];
    __shared__ int   s_npos;
    __shared__ float sred[8];
    __shared__ int   cred[8];
    __shared__ float fsred[8];
    __shared__ float fcred[8];
    __shared__ int   s_islast;

    const int i = blockIdx.x;
    const int t = threadIdx.x;          // 0..255
    const int lane = t & 31;
    const int w = t >> 5;

    reinterpret_cast<float2*>(drow)[t] =
        reinterpret_cast<const float2*>(g_dist + i * N)[t];
    reinterpret_cast<int2*>(lab)[t] =
        reinterpret_cast<const int2*>(labels)[t];
    __syncthreads();

    const int li = lab[i];
    const bool m0 = (lab[t] == li) && (t != i);
    const bool m1 = (lab[t + 256] == li) && (t + 256 != i);

    // deterministic compaction of positives
    unsigned b0 = __ballot_sync(0xFFFFFFFFu, m0);
    unsigned b1 = __ballot_sync(0xFFFFFFFFu, m1);
    if (lane == 0) { segcnt[w] = __popc(b0); segcnt[8 + w] = __popc(b1); }
    __syncthreads();
    if (m0) {
        int off = 0;
        for (int s = 0; s < w; s++) off += segcnt[s];
        off += __popc(b0 & ((1u << lane) - 1u));
        posj[off] = t;
    }
    if (m1) {
        int off = 0;
        for (int s = 0; s < 8 + w; s++) off += segcnt[s];
        off += __popc(b1 & ((1u << lane) - 1u));
        posj[off] = t + 256;
    }
    if (t == 0) {
        int tot = 0;
        for (int s = 0; s < 16; s++) tot += segcnt[s];
        s_npos = tot;
    }
    __syncthreads();

    const int npos = s_npos;
    const float d0 = drow[t];
    const float d1 = drow[t + 256];
    const bool n0 = (lab[t] != li);
    const bool n1 = (lab[t + 256] != li);

    float sum = 0.f;
    int cnt = 0;
    for (int p = 0; p < npos; p++) {
        float a = drow[posj[p]] + 1.0f;   // d_ij + margin (smem broadcast)
        if (n0) {
            float v = a - d0;
            if (v > 0.f) sum += v;
            if (v > 1e-16f) cnt++;
        }
        if (n1) {
            float v = a - d1;
            if (v > 0.f) sum += v;
            if (v > 1e-16f) cnt++;
        }
    }

    // deterministic block reduction
#pragma unroll
    for (int o = 16; o > 0; o >>= 1) {
        sum += __shfl_down_sync(0xFFFFFFFFu, sum, o);
        cnt += __shfl_down_sync(0xFFFFFFFFu, cnt, o);
    }
    if (lane == 0) { sred[w] = sum; cred[w] = cnt; }
    __syncthreads();
    if (t == 0) {
        float s = 0.f; int c = 0;
#pragma unroll
        for (int k = 0; k < 8; k++) { s += sred[k]; c += cred[k]; }
        g_psum[i] = s;
        g_pcnt[i] = (float)c;
        __threadfence();
        int old = atomicAdd(&g_done, 1);
        s_islast = (old == gridDim.x - 1) ? 1 : 0;
    }
    __syncthreads();

    // last block: final deterministic reduction over all 512 partials
    if (s_islast) {
        __threadfence();
        float s = g_psum[t] + g_psum[t + 256];
        float c = g_pcnt[t] + g_pcnt[t + 256];
#pragma unroll
        for (int o = 16; o > 0; o >>= 1) {
            s += __shfl_down_sync(0xFFFFFFFFu, s, o);
            c += __shfl_down_sync(0xFFFFFFFFu, c, o);
        }
        if (lane == 0) { fsred[w] = s; fcred[w] = c; }
        __syncthreads();
        if (t == 0) {
            float S = 0.f, C = 0.f;
#pragma unroll
            for (int k = 0; k < 8; k++) { S += fsred[k]; C += fcred[k]; }
            out[0] = S / (C + 1e-16f);
            g_done = 0;   // reset for next graph replay
        }
    }
}

// ---------------------------------------------------------------------------
extern "C" void kernel_launch(void* const* d_in, const int* in_sizes, int n_in,
                              void* d_out, int out_size) {
    const float* x      = (const float*)d_in[0];   // (512, 256) float32
    const int*   labels = (const int*)d_in[1];     // (512,) int32
    float* out = (float*)d_out;

    dist_kernel<<<136, 256>>>(x);          // 16x16 tile triangle
    triplet_kernel<<<N, 256>>>(labels, out);
}